// round 5
// baseline (speedup 1.0000x reference)
#include <cuda_runtime.h>
#include <cstdint>

#define NEG_INF (-1e30f)

constexpr int B = 32;
constexpr int L = 4096;
constexpr int D = 1024;

constexpr int THREADS1 = 256;
constexpr int WARPS1 = 8;
constexpr int ROWS_PER_BLOCK = 256;
constexpr int NCHUNK = L / ROWS_PER_BLOCK;   // 16
constexpr int NPART = B * NCHUNK;            // 512
constexpr int RB = 16;                       // rows per round

constexpr int P2_SPLIT = 8;                  // 128 cols per block
constexpr int THREADS2 = 256;

// Scratch (no allocations allowed in kernel_launch)
__device__ __align__(16) float g_scores[B * L];
__device__ __align__(16) float g_pacc[NPART][D];
__device__ float g_pm[NPART];
__device__ float g_pz[NPART];

// ---- packed f32x2 helpers (PTX-only; ptxas never emits FFMA2 from C++) ----
__device__ __forceinline__ unsigned long long f2fma(unsigned long long a,
                                                    unsigned long long b,
                                                    unsigned long long c) {
    unsigned long long d;
    asm("fma.rn.f32x2 %0, %1, %2, %3;" : "=l"(d) : "l"(a), "l"(b), "l"(c));
    return d;
}
__device__ __forceinline__ unsigned long long f2mul(unsigned long long a,
                                                    unsigned long long b) {
    unsigned long long d;
    asm("mul.rn.f32x2 %0, %1, %2;" : "=l"(d) : "l"(a), "l"(b));
    return d;
}
__device__ __forceinline__ float f2sum(unsigned long long a) {
    unsigned lo, hi;
    asm("mov.b64 {%0, %1}, %2;" : "=r"(lo), "=r"(hi) : "l"(a));
    return __uint_as_float(lo) + __uint_as_float(hi);
}
__device__ __forceinline__ unsigned long long f2bcast(float f) {
    unsigned long long d;
    unsigned u = __float_as_uint(f);
    asm("mov.b64 %0, {%1, %1};" : "=l"(d) : "r"(u));
    return d;
}

__global__ __launch_bounds__(THREADS1, 2)
void attn_pool_pass1(const float* __restrict__ seq,
                     const float* __restrict__ vec,
                     const int*   __restrict__ mask) {
    const int blk   = blockIdx.x;
    const int b     = blk / NCHUNK;
    const int chunk = blk % NCHUNK;
    const int tid   = threadIdx.x;
    const int wid   = tid >> 5;
    const int lane  = tid & 31;
    const int row0  = chunk * ROWS_PER_BLOCK;

    __shared__ int row_list[ROWS_PER_BLOCK];
    __shared__ int cnt_sh[WARPS1];
    __shared__ __align__(16) float sp[2][RB][WARPS1]; // [parity][row][warp]

    // ---- compaction of unmasked rows (256 rows, 256 threads) ----
    const int mk = mask[(size_t)b * L + row0 + tid];
    const unsigned bal = __ballot_sync(0xffffffffu, mk != 0);
    if (lane == 0) cnt_sh[wid] = __popc(bal);
    if (mk == 0) g_scores[(size_t)b * L + row0 + tid] = NEG_INF;
    __syncthreads();
    int base = 0, n_rows = 0;
#pragma unroll
    for (int j = 0; j < WARPS1; j++) {
        if (j < wid) base += cnt_sh[j];
        n_rows += cnt_sh[j];
    }
    if (mk != 0)
        row_list[base + __popc(bal & ((1u << lane) - 1u))] = tid;
    __syncthreads();

    // warp w owns cols [w*128,(w+1)*128); lane owns one 16B chunk
    const int fbase = wid * 32 + lane;   // 16-byte-unit index within a row
    const ulonglong2 v =
        reinterpret_cast<const ulonglong2*>(vec + (size_t)b * D)[fbase];

    float m = NEG_INF, z = 0.0f;
    ulonglong2 a = make_ulonglong2(0ull, 0ull);

    const ulonglong2* sbase =
        reinterpret_cast<const ulonglong2*>(seq + ((size_t)b * L + row0) * D);
    const int nR = (n_rows + RB - 1) / RB;

    for (int rd = 0; rd < nR; rd++) {
        const int p    = rd & 1;
        const int idx0 = rd * RB;

        // front-batched: 16 LDG.128 per warp
        ulonglong2 x[RB];
#pragma unroll
        for (int r = 0; r < RB; r++) {
            const int ii = idx0 + r;
            const int rl = row_list[(ii < n_rows) ? ii : 0];
            x[r] = sbase[(size_t)rl * (D / 4) + fbase];
        }

        // per-lane partial dots (f32x2)
        float cur[RB];
#pragma unroll
        for (int r = 0; r < RB; r++) {
            unsigned long long d2 = f2mul(x[r].x, v.x);
            d2 = f2fma(x[r].y, v.y, d2);
            cur[r] = f2sum(d2);
        }

        // multi-value butterfly: absorb value-bit k into lane-bit k
#pragma unroll
        for (int stage = 0; stage < 4; stage++) {
            const int off = 1 << stage;
            const unsigned bit = (lane >> stage) & 1u;
            const int n = RB >> (stage + 1);
#pragma unroll
            for (int i = 0; i < n; i++) {
                const float keep = bit ? cur[2 * i + 1] : cur[2 * i];
                const float send = bit ? cur[2 * i] : cur[2 * i + 1];
                cur[i] = keep + __shfl_xor_sync(0xffffffffu, send, off);
            }
        }
        float t = cur[0] + __shfl_xor_sync(0xffffffffu, cur[0], 16);
        // lane holds this warp's slice-partial for row = lane&15
        if (lane < RB) sp[p][lane][wid] = t;
        __syncthreads();

        // full dot for row = lane&15 (two LDS.128)
        const int row = lane & (RB - 1);
        const float4* sq = reinterpret_cast<const float4*>(&sp[p][row][0]);
        const float4 s0 = sq[0], s1 = sq[1];
        const float dot = (s0.x + s0.y) + (s0.z + s0.w)
                        + (s1.x + s1.y) + (s1.z + s1.w);

        if (wid == 0 && lane < RB && idx0 + lane < n_rows)
            g_scores[(size_t)b * L + row0 + row_list[idx0 + lane]] = dot;

        const float dv = (idx0 + row < n_rows) ? dot : NEG_INF;

        float rmax = dv;
        rmax = fmaxf(rmax, __shfl_xor_sync(0xffffffffu, rmax, 1));
        rmax = fmaxf(rmax, __shfl_xor_sync(0xffffffffu, rmax, 2));
        rmax = fmaxf(rmax, __shfl_xor_sync(0xffffffffu, rmax, 4));
        rmax = fmaxf(rmax, __shfl_xor_sync(0xffffffffu, rmax, 8));

        const float mnew  = fmaxf(m, rmax);
        const float scale = __expf(m - mnew);
        const float e     = __expf(dv - mnew);
        float es = e;
        es += __shfl_xor_sync(0xffffffffu, es, 1);
        es += __shfl_xor_sync(0xffffffffu, es, 2);
        es += __shfl_xor_sync(0xffffffffu, es, 4);
        es += __shfl_xor_sync(0xffffffffu, es, 8);
        z = z * scale + es;

        const unsigned long long s2v = f2bcast(scale);
        a.x = f2mul(a.x, s2v);
        a.y = f2mul(a.y, s2v);
#pragma unroll
        for (int r = 0; r < RB; r++) {
            const unsigned long long e2 =
                f2bcast(__shfl_sync(0xffffffffu, e, r));
            a.x = f2fma(x[r].x, e2, a.x);
            a.y = f2fma(x[r].y, e2, a.y);
        }
        m = mnew;
    }

    // each warp writes its own 128-col slice; m,z identical across warps
    reinterpret_cast<ulonglong2*>(g_pacc[blk])[fbase] = a;
    if (tid == 0) { g_pm[blk] = m; g_pz[blk] = z; }
}

__global__ __launch_bounds__(THREADS2)
void attn_pool_pass2(float* __restrict__ out_pooled,   // [B, D]
                     float* __restrict__ out_weights)  // [B, L]
{
    const int b    = blockIdx.x / P2_SPLIT;
    const int part = blockIdx.x % P2_SPLIT;
    const int tid  = threadIdx.x;
    const int lane = tid & 31;

    __shared__ float sh_sc[NCHUNK];
    __shared__ float sh_stats[2];
    __shared__ __align__(16) float4 sh_pool[8][32];

    if (tid < 32) {
        const float pm = (lane < NCHUNK) ? g_pm[b * NCHUNK + lane] : NEG_INF;
        const float pz = (lane < NCHUNK) ? g_pz[b * NCHUNK + lane] : 0.0f;
        float mloc = pm;
#pragma unroll
        for (int o = 8; o > 0; o >>= 1)
            mloc = fmaxf(mloc, __shfl_xor_sync(0xffffffffu, mloc, o));
        mloc = fmaxf(mloc, __shfl_xor_sync(0xffffffffu, mloc, 16));
        const float s = __expf(pm - mloc);
        if (lane < NCHUNK) sh_sc[lane] = s;
        float zl = pz * s;
#pragma unroll
        for (int o = 8; o > 0; o >>= 1)
            zl += __shfl_xor_sync(0xffffffffu, zl, o);
        zl += __shfl_xor_sync(0xffffffffu, zl, 16);
        if (lane == 0) { sh_stats[0] = mloc; sh_stats[1] = 1.0f / zl; }
    }
    __syncthreads();
    const float m_f  = sh_stats[0];
    const float invZ = sh_stats[1];

    // pooled: 128 cols per block as 32 float4; 8 groups x 2 partials
    {
        const int c4 = tid & 31;
        const int g  = tid >> 5;
        float4 s = make_float4(0.f, 0.f, 0.f, 0.f);
#pragma unroll
        for (int jj = 0; jj < NCHUNK / 8; jj++) {
            const int j = g * (NCHUNK / 8) + jj;
            const float4 t = *reinterpret_cast<const float4*>(
                &g_pacc[b * NCHUNK + j][part * 128 + 4 * c4]);
            const float w = sh_sc[j];
            s.x += w * t.x; s.y += w * t.y; s.z += w * t.z; s.w += w * t.w;
        }
        sh_pool[g][c4] = s;
    }
    __syncthreads();
    if (tid < 32) {
        float4 s = sh_pool[0][tid];
#pragma unroll
        for (int g = 1; g < 8; g++) {
            const float4 t = sh_pool[g][tid];
            s.x += t.x; s.y += t.y; s.z += t.z; s.w += t.w;
        }
        s.x *= invZ; s.y *= invZ; s.z *= invZ; s.w *= invZ;
        reinterpret_cast<float4*>(out_pooled)[b * (D / 4) + part * 32 + tid] = s;
    }

    // weights: 512 per block as float2 per thread
    {
        const int l0 = part * (L / P2_SPLIT) + tid * 2;
        const float2 sc2 =
            *reinterpret_cast<const float2*>(&g_scores[(size_t)b * L + l0]);
        float2 w2;
        w2.x = __expf(sc2.x - m_f) * invZ;
        w2.y = __expf(sc2.y - m_f) * invZ;
        *reinterpret_cast<float2*>(&out_weights[(size_t)b * L + l0]) = w2;
    }
}

extern "C" void kernel_launch(void* const* d_in, const int* in_sizes, int n_in,
                              void* d_out, int out_size) {
    const float* seq  = (const float*)d_in[0];
    const float* vec  = (const float*)d_in[1];
    const int*   mask = (const int*)d_in[2];

    float* out_pooled  = (float*)d_out;               // [B, D]
    float* out_weights = out_pooled + (size_t)B * D;  // [B, L]

    attn_pool_pass1<<<B * NCHUNK, THREADS1>>>(seq, vec, mask);
    attn_pool_pass2<<<B * P2_SPLIT, THREADS2>>>(out_pooled, out_weights);
}